// round 14
// baseline (speedup 1.0000x reference)
#include <cuda_runtime.h>
#include <cuda_fp16.h>
#include <cstdint>
#include <cstddef>

#define MEMB   8
#define BATCHI 4096
#define E_DIM  512
#define H_DIM  1024
#define V_DIM  4096
#define ROWS   (MEMB * BATCHI)   // 32768

// ---------------- scratch (device globals: allocation-free) ----------------
__device__ __half g_xh [(size_t)ROWS * E_DIM];          // fp16 x
__device__ __half g_w1h[(size_t)MEMB * E_DIM * H_DIM];  // fp16 W1
__device__ __half g_w2h[(size_t)MEMB * H_DIM * V_DIM];  // fp16 W2
__device__ __half g_h16[(size_t)ROWS * H_DIM];          // fp16 hidden (pre-LN)
__device__ __half g_hh [(size_t)ROWS * H_DIM];          // fp16 hidden (GEMM2 in)

// ---------------- helpers ----------------
__device__ __forceinline__ uint32_t smem_u32(const void* p) {
    uint32_t a;
    asm("{ .reg .u64 t; cvta.to.shared.u64 t, %1; cvt.u32.u64 %0, t; }"
        : "=r"(a) : "l"(p));
    return a;
}
__device__ __forceinline__ void cp16_cg(uint32_t s, const void* g) {   // L1-bypass
    asm volatile("cp.async.cg.shared.global [%0], [%1], 16;" :: "r"(s), "l"(g));
}
__device__ __forceinline__ void cp16_ca(uint32_t s, const void* g) {   // L1-alloc
    asm volatile("cp.async.ca.shared.global [%0], [%1], 16;" :: "r"(s), "l"(g));
}
__device__ __forceinline__ void cp_commit() {
    asm volatile("cp.async.commit_group;" ::: "memory");
}
__device__ __forceinline__ void cp_wait0() {
    asm volatile("cp.async.wait_group 0;" ::: "memory");
}
__device__ __forceinline__ void ldsm_x4(uint32_t (&r)[4], uint32_t addr) {
    asm volatile("ldmatrix.sync.aligned.m8n8.x4.shared.b16 {%0,%1,%2,%3}, [%4];"
                 : "=r"(r[0]), "=r"(r[1]), "=r"(r[2]), "=r"(r[3]) : "r"(addr));
}
// x4 transposed: two k-halves x two adjacent n-groups
__device__ __forceinline__ void ldsm_x4_t(uint32_t& r0, uint32_t& r1,
                                          uint32_t& r2, uint32_t& r3,
                                          uint32_t addr) {
    asm volatile("ldmatrix.sync.aligned.m8n8.x4.trans.shared.b16 {%0,%1,%2,%3}, [%4];"
                 : "=r"(r0), "=r"(r1), "=r"(r2), "=r"(r3) : "r"(addr));
}
__device__ __forceinline__ void mma_f16(float (&d)[4], const uint32_t (&a)[4],
                                        const uint32_t (&b)[2]) {
    asm volatile(
        "mma.sync.aligned.m16n8k16.row.col.f32.f16.f16.f32 "
        "{%0,%1,%2,%3}, {%4,%5,%6,%7}, {%8,%9}, {%0,%1,%2,%3};\n"
        : "+f"(d[0]), "+f"(d[1]), "+f"(d[2]), "+f"(d[3])
        : "r"(a[0]), "r"(a[1]), "r"(a[2]), "r"(a[3]), "r"(b[0]), "r"(b[1]));
}
__device__ __forceinline__ void stcs_f2(float* p, float2 v) {
    asm volatile("st.global.cs.v2.f32 [%0], {%1, %2};" :: "l"(p), "f"(v.x), "f"(v.y)
                 : "memory");
}

// ---------------- tiling (round-12 champion config) ----------------
#define BM   128
#define BN   128
#define BK   64            // fp16 k-depth per tile (4 ks steps of 16)
#define NTHREADS 128       // 4 warps (2m x 2n), warp tile 64x64
#define STAGES 2
#define A_ROW_B  144       // 64 halfs (128B) + 16B pad, conflict-free ldmatrix
#define B_ROW_B  272       // 128 halfs (256B) + 16B pad, conflict-free ldmatrix
#define A_ST_B   (BM * A_ROW_B)              // 18432
#define B_ST_B   (BK * B_ROW_B)              // 17408
#define STAGE_B  (A_ST_B + B_ST_B)           // 35840
#define SMEM_TOTAL (STAGES * STAGE_B)        // 71680 (x2 CTA = 143360)
#define A_CHUNKS (BM * BK * 2 / 16)          // 1024
#define B_CHUNKS (BK * BN * 2 / 16)          // 1024

// one stage of cp.async: 16 chunks/thread @ 128 threads.
// A via .cg (streaming); B via .ca (L1-cached, shared with co-resident CTA).
__device__ __forceinline__ void load_stage(uint32_t sbase, int st,
                                           const __half* __restrict__ Ag,
                                           const __half* __restrict__ Bg,
                                           int K, int Ntot, int tid) {
    const uint32_t sA = sbase + st * STAGE_B;
    const uint32_t sB = sA + A_ST_B;
#pragma unroll
    for (int j = 0; j < (A_CHUNKS + B_CHUNKS) / NTHREADS; j++) {
        const int c = tid + j * NTHREADS;
        if (c < A_CHUNKS) {
            const int row = c >> 3, q = c & 7;        // 8 chunks per A row
            cp16_cg(sA + (uint32_t)(row * A_ROW_B + q * 16),
                    Ag + (size_t)row * K + q * 8);
        } else {
            const int b = c - A_CHUNKS;
            const int k = b >> 4, q = b & 15;         // 16 chunks per B row
            cp16_ca(sB + (uint32_t)(k * B_ROW_B + q * 16),
                    Bg + (size_t)k * Ntot + q * 8);
        }
    }
}

// load one ks-step's fragments (warp tile 64x64); B via x4.trans
__device__ __forceinline__ void frag_load(uint32_t (&af)[4][4], uint32_t (&bf)[8][2],
                                          uint32_t sA, uint32_t sB, int ks,
                                          int wm, int wn,
                                          uint32_t a_lane_off, uint32_t b_lane_off) {
#pragma unroll
    for (int mt = 0; mt < 4; mt++) {
        ldsm_x4(af[mt], sA + (uint32_t)((wm * 64 + mt * 16) * A_ROW_B + ks * 32)
                        + a_lane_off);
    }
#pragma unroll
    for (int nt2 = 0; nt2 < 4; nt2++) {
        ldsm_x4_t(bf[2 * nt2][0], bf[2 * nt2][1],
                  bf[2 * nt2 + 1][0], bf[2 * nt2 + 1][1],
                  sB + (uint32_t)(ks * 16 * B_ROW_B + (wn * 64 + nt2 * 16) * 2)
                     + b_lane_off);
    }
}

// -------- GEMM: C[row,n] = sum_k A[row,k]*W[m,k,n] + bias[m,n] (fp16 in)
// HALF_OUT=1 -> fp16 output (GEMM1), else fp32 streaming stores (GEMM2).
// 128 threads = 4 warps (2m x 2n), warp tile 64x64, 2 CTAs/SM.
template <int HALF_OUT>
__launch_bounds__(NTHREADS, 2)
__global__ void gemm_f16(const __half* __restrict__ A,
                         const __half* __restrict__ W,
                         const float* __restrict__ bias,
                         float* __restrict__ Cf,
                         __half* __restrict__ Ch,
                         int K, int Ntot, int NT) {
    extern __shared__ __align__(16) char smc[];
    const uint32_t sbase = smem_u32(smc);

    const int tid  = threadIdx.x;
    const int lane = tid & 31;
    const int warp = tid >> 5;
    const int wm   = warp >> 1;      // 0..1
    const int wn   = warp & 1;       // 0..1
    const int g    = lane >> 2;      // 0..7
    const int r    = lane & 3;       // 0..3

    const int brow   = blockIdx.x * BM;   // row tile fastest
    const int bcol   = blockIdx.y * BN;
    const int member = brow >> 12;

    const __half* Ag0 = A + (size_t)brow * K;
    const __half* Bg0 = W + (size_t)member * K * Ntot + bcol;

    float acc[4][8][4];
#pragma unroll
    for (int i = 0; i < 4; i++)
#pragma unroll
        for (int j = 0; j < 8; j++)
#pragma unroll
            for (int c = 0; c < 4; c++) acc[i][j][c] = 0.f;

    const uint32_t a_lane_off =
        (uint32_t)((lane & 15) * A_ROW_B + (lane >> 4) * 16);
    const uint32_t b_lane_off =
        (uint32_t)((lane & 15) * B_ROW_B + (lane >> 4) * 16);

    // prologue: stage 0 = tile 0
    load_stage(sbase, 0, Ag0, Bg0, K, Ntot, tid);
    cp_commit();

    uint32_t af[2][4][4];
    uint32_t bf[2][8][2];

    for (int t = 0; t < NT; t++) {
        cp_wait0();          // tile t landed (only group pending)
        __syncthreads();     // visible to all; all done reading other buffer

        const uint32_t sA = sbase + (t & 1) * STAGE_B;
        const uint32_t sB = sA + A_ST_B;

        // ks0 LDSM first: latency hides under cp.async issue below
        frag_load(af[0], bf[0], sA, sB, 0, wm, wn, a_lane_off, b_lane_off);

        if (t + 1 < NT) {
            load_stage(sbase, (t + 1) & 1, Ag0 + (t + 1) * BK,
                       Bg0 + (size_t)(t + 1) * BK * Ntot, K, Ntot, tid);
        }
        cp_commit();

        // software-pipelined ks loop: prefetch ks+1 frags before ks MMAs
#pragma unroll
        for (int ks = 0; ks < 4; ks++) {
            const int cur = ks & 1;
            if (ks < 3) {
                frag_load(af[cur ^ 1], bf[cur ^ 1], sA, sB, ks + 1,
                          wm, wn, a_lane_off, b_lane_off);
            }
#pragma unroll
            for (int mt = 0; mt < 4; mt++)
#pragma unroll
                for (int nt = 0; nt < 8; nt++)
                    mma_f16(acc[mt][nt], af[cur][mt], bf[cur][nt]);
        }
    }

    // epilogue: bias + store
    const float* bm = bias + (size_t)member * Ntot + bcol;
#pragma unroll
    for (int mt = 0; mt < 4; mt++) {
        const int row0 = brow + wm * 64 + mt * 16 + g;
#pragma unroll
        for (int nt = 0; nt < 8; nt++) {
            const int col0 = bcol + wn * 64 + nt * 8 + r * 2;
            const float bx0 = __ldg(bm + (col0 - bcol));
            const float bx1 = __ldg(bm + (col0 - bcol) + 1);
            if (HALF_OUT) {
                __half2 v0 = __floats2half2_rn(acc[mt][nt][0] + bx0,
                                               acc[mt][nt][1] + bx1);
                __half2 v1 = __floats2half2_rn(acc[mt][nt][2] + bx0,
                                               acc[mt][nt][3] + bx1);
                *(__half2*)(Ch + (size_t)row0 * Ntot + col0) = v0;
                *(__half2*)(Ch + (size_t)(row0 + 8) * Ntot + col0) = v1;
            } else {
                float2 v0, v1;
                v0.x = acc[mt][nt][0] + bx0;
                v0.y = acc[mt][nt][1] + bx1;
                v1.x = acc[mt][nt][2] + bx0;
                v1.y = acc[mt][nt][3] + bx1;
                stcs_f2(Cf + (size_t)row0 * Ntot + col0, v0);        // streaming
                stcs_f2(Cf + (size_t)(row0 + 8) * Ntot + col0, v1);  // (no L2 keep)
            }
        }
    }
}

// ---------------- pre-pass: all three fp32 -> fp16 conversions, one launch ----
#define XN8  (ROWS * E_DIM / 8)
#define W1N8 (MEMB * E_DIM * H_DIM / 8)
#define W2N8 (MEMB * H_DIM * V_DIM / 8)

__global__ void convert_all(const float* __restrict__ x,
                            const float* __restrict__ W1,
                            const float* __restrict__ W2) {
    int i = blockIdx.x * blockDim.x + threadIdx.x;
    const float* src;
    __half* dst;
    if (i < XN8) {
        src = x; dst = g_xh;
    } else if (i < XN8 + W1N8) {
        i -= XN8; src = W1; dst = g_w1h;
    } else {
        i -= XN8 + W1N8;
        if (i >= W2N8) return;
        src = W2; dst = g_w2h;
    }
    float4 a = ((const float4*)src)[2 * i];
    float4 b = ((const float4*)src)[2 * i + 1];
    __half2 h[4];
    h[0] = __floats2half2_rn(a.x, a.y);
    h[1] = __floats2half2_rn(a.z, a.w);
    h[2] = __floats2half2_rn(b.x, b.y);
    h[3] = __floats2half2_rn(b.z, b.w);
    ((uint4*)dst)[i] = *(uint4*)h;
}

// ------------- fused LayerNorm + SiLU; fp16 in (g_h16), fp16 out (g_hh) -----
// one WARP per row (32 halfs/lane); pure shfl reduction, no smem/barrier.
// 256 threads = 8 rows per CTA; grid = ROWS/8.
__launch_bounds__(256)
__global__ void ln_silu_kernel(const float* __restrict__ ln_w,
                               const float* __restrict__ ln_b) {
    const int row  = blockIdx.x * 8 + (threadIdx.x >> 5);
    const int lane = threadIdx.x & 31;
    const int m    = row >> 12;
    const __half* hp = g_h16 + (size_t)row * H_DIM;
    __half* op = g_hh + (size_t)row * H_DIM;

    // load 32 halfs = 4 uint4
    __half2 hv[16];
#pragma unroll
    for (int v = 0; v < 4; v++)
        *((uint4*)hv + v) = *(const uint4*)(hp + lane * 32 + v * 8);

    float xv[32];
#pragma unroll
    for (int i = 0; i < 16; i++) {
        float2 f = __half22float2(hv[i]);
        xv[2 * i] = f.x; xv[2 * i + 1] = f.y;
    }

    float s = 0.f, q = 0.f;
#pragma unroll
    for (int i = 0; i < 32; i++) { s += xv[i]; q += xv[i] * xv[i]; }
#pragma unroll
    for (int o = 16; o; o >>= 1) {
        s += __shfl_xor_sync(0xffffffffu, s, o);
        q += __shfl_xor_sync(0xffffffffu, q, o);
    }

    const float mu  = s * (1.0f / H_DIM);
    const float var = q * (1.0f / H_DIM) - mu * mu;
    const float inv = rsqrtf(var + 1e-5f);

    const float* wp = ln_w + (size_t)m * H_DIM + lane * 32;
    const float* bp = ln_b + (size_t)m * H_DIM + lane * 32;

    __half2 o2[16];
#pragma unroll
    for (int i = 0; i < 16; i++) {
        float w0 = wp[2 * i], w1 = wp[2 * i + 1];
        float b0 = bp[2 * i], b1 = bp[2 * i + 1];
        float v0 = (xv[2 * i] - mu) * inv * w0 + b0;
        float v1 = (xv[2 * i + 1] - mu) * inv * w1 + b1;
        v0 = v0 / (1.f + __expf(-v0));
        v1 = v1 / (1.f + __expf(-v1));
        o2[i] = __floats2half2_rn(v0, v1);
    }
#pragma unroll
    for (int v = 0; v < 4; v++)
        *(uint4*)(op + lane * 32 + v * 8) = *((uint4*)o2 + v);
}

// ---------------- launch ----------------
extern "C" void kernel_launch(void* const* d_in, const int* in_sizes, int n_in,
                              void* d_out, int out_size) {
    const float* x  = (const float*)d_in[0];
    const float* W1 = (const float*)d_in[1];
    const float* b1 = (const float*)d_in[2];
    const float* lw = (const float*)d_in[3];
    const float* lb = (const float*)d_in[4];
    const float* W2 = (const float*)d_in[5];
    const float* b2 = (const float*)d_in[6];
    float* out = (float*)d_out;

    __half *xh, *w1h, *w2h, *hh, *h16;
    cudaGetSymbolAddress((void**)&xh,  g_xh);
    cudaGetSymbolAddress((void**)&w1h, g_w1h);
    cudaGetSymbolAddress((void**)&w2h, g_w2h);
    cudaGetSymbolAddress((void**)&h16, g_h16);
    cudaGetSymbolAddress((void**)&hh,  g_hh);

    cudaFuncSetAttribute(gemm_f16<1>, cudaFuncAttributeMaxDynamicSharedMemorySize,
                         SMEM_TOTAL);
    cudaFuncSetAttribute(gemm_f16<0>, cudaFuncAttributeMaxDynamicSharedMemorySize,
                         SMEM_TOTAL);

    // pre-pass: fp32 -> fp16 (x, W1, W2 in one launch)
    const int total8 = XN8 + W1N8 + W2N8;
    convert_all<<<(total8 + 511) / 512, 512>>>(x, W1, W2);

    // GEMM1: [32768,512] x [8: 512->1024] -> h16 (+b1), fp16 out
    gemm_f16<1><<<dim3(ROWS / BM, H_DIM / BN), NTHREADS, SMEM_TOTAL>>>(
        xh, w1h, b1, nullptr, h16, E_DIM, H_DIM, E_DIM / BK);
    // LayerNorm + SiLU, fp16 -> fp16 (warp per row)
    ln_silu_kernel<<<ROWS / 8, 256>>>(lw, lb);
    // GEMM2: [32768,1024] x [8: 1024->4096] -> out (+b2), fp32 streaming out
    gemm_f16<0><<<dim3(ROWS / BM, V_DIM / BN), NTHREADS, SMEM_TOTAL>>>(
        hh, w2h, b2, out, nullptr, H_DIM, V_DIM, H_DIM / BK);
}

// round 15
// speedup vs baseline: 1.2153x; 1.2153x over previous
#include <cuda_runtime.h>
#include <cuda_fp16.h>
#include <cstdint>
#include <cstddef>

#define MEMB   8
#define BATCHI 4096
#define E_DIM  512
#define H_DIM  1024
#define V_DIM  4096
#define ROWS   (MEMB * BATCHI)   // 32768

// ---------------- scratch (device globals: allocation-free) ----------------
__device__ __half g_xh [(size_t)ROWS * E_DIM];          // fp16 x
__device__ __half g_w1h[(size_t)MEMB * E_DIM * H_DIM];  // fp16 W1
__device__ __half g_w2h[(size_t)MEMB * H_DIM * V_DIM];  // fp16 W2
__device__ __half g_h16[(size_t)ROWS * H_DIM];          // fp16 hidden (pre-LN)
__device__ __half g_hh [(size_t)ROWS * H_DIM];          // fp16 hidden (GEMM2 in)

// ---------------- helpers ----------------
__device__ __forceinline__ uint32_t smem_u32(const void* p) {
    uint32_t a;
    asm("{ .reg .u64 t; cvta.to.shared.u64 t, %1; cvt.u32.u64 %0, t; }"
        : "=r"(a) : "l"(p));
    return a;
}
__device__ __forceinline__ void cp16_cg(uint32_t s, const void* g) {   // L1-bypass
    asm volatile("cp.async.cg.shared.global [%0], [%1], 16;" :: "r"(s), "l"(g));
}
__device__ __forceinline__ void cp16_ca(uint32_t s, const void* g) {   // L1-alloc
    asm volatile("cp.async.ca.shared.global [%0], [%1], 16;" :: "r"(s), "l"(g));
}
__device__ __forceinline__ void cp_commit() {
    asm volatile("cp.async.commit_group;" ::: "memory");
}
__device__ __forceinline__ void cp_wait0() {
    asm volatile("cp.async.wait_group 0;" ::: "memory");
}
__device__ __forceinline__ void ldsm_x4(uint32_t (&r)[4], uint32_t addr) {
    asm volatile("ldmatrix.sync.aligned.m8n8.x4.shared.b16 {%0,%1,%2,%3}, [%4];"
                 : "=r"(r[0]), "=r"(r[1]), "=r"(r[2]), "=r"(r[3]) : "r"(addr));
}
// x4 transposed: two k-halves x two adjacent n-groups
__device__ __forceinline__ void ldsm_x4_t(uint32_t& r0, uint32_t& r1,
                                          uint32_t& r2, uint32_t& r3,
                                          uint32_t addr) {
    asm volatile("ldmatrix.sync.aligned.m8n8.x4.trans.shared.b16 {%0,%1,%2,%3}, [%4];"
                 : "=r"(r0), "=r"(r1), "=r"(r2), "=r"(r3) : "r"(addr));
}
__device__ __forceinline__ void mma_f16(float (&d)[4], const uint32_t (&a)[4],
                                        const uint32_t (&b)[2]) {
    asm volatile(
        "mma.sync.aligned.m16n8k16.row.col.f32.f16.f16.f32 "
        "{%0,%1,%2,%3}, {%4,%5,%6,%7}, {%8,%9}, {%0,%1,%2,%3};\n"
        : "+f"(d[0]), "+f"(d[1]), "+f"(d[2]), "+f"(d[3])
        : "r"(a[0]), "r"(a[1]), "r"(a[2]), "r"(a[3]), "r"(b[0]), "r"(b[1]));
}
__device__ __forceinline__ void stcs_f2(float* p, float2 v) {
    asm volatile("st.global.cs.v2.f32 [%0], {%1, %2};" :: "l"(p), "f"(v.x), "f"(v.y)
                 : "memory");
}

// ---------------- tiling (round-12 champion config) ----------------
#define BM   128
#define BN   128
#define BK   64            // fp16 k-depth per tile (4 ks steps of 16)
#define NTHREADS 128       // 4 warps (2m x 2n), warp tile 64x64
#define STAGES 2
#define A_ROW_B  144       // 64 halfs (128B) + 16B pad, conflict-free ldmatrix
#define B_ROW_B  272       // 128 halfs (256B) + 16B pad, conflict-free ldmatrix
#define A_ST_B   (BM * A_ROW_B)              // 18432
#define B_ST_B   (BK * B_ROW_B)              // 17408
#define STAGE_B  (A_ST_B + B_ST_B)           // 35840
#define SMEM_TOTAL (STAGES * STAGE_B)        // 71680 (x2 CTA = 143360)
#define A_CHUNKS (BM * BK * 2 / 16)          // 1024
#define B_CHUNKS (BK * BN * 2 / 16)          // 1024

// one quarter of a stage: 4 chunks/thread. q=0,1 cover A; q=2,3 cover B.
__device__ __forceinline__ void load_quarter(uint32_t sbase, int st,
                                             const __half* __restrict__ Ag,
                                             const __half* __restrict__ Bg,
                                             int K, int Ntot, int tid, int q) {
    const uint32_t sA = sbase + st * STAGE_B;
    const uint32_t sB = sA + A_ST_B;
#pragma unroll
    for (int jj = 0; jj < 4; jj++) {
        const int c = tid + (q * 4 + jj) * NTHREADS;
        if (c < A_CHUNKS) {
            const int row = c >> 3, qq = c & 7;       // 8 chunks per A row
            cp16_cg(sA + (uint32_t)(row * A_ROW_B + qq * 16),
                    Ag + (size_t)row * K + qq * 8);
        } else {
            const int b = c - A_CHUNKS;
            const int k = b >> 4, qq = b & 15;        // 16 chunks per B row
            cp16_ca(sB + (uint32_t)(k * B_ROW_B + qq * 16),
                    Bg + (size_t)k * Ntot + qq * 8);
        }
    }
}

// full stage (prologue only)
__device__ __forceinline__ void load_stage(uint32_t sbase, int st,
                                           const __half* __restrict__ Ag,
                                           const __half* __restrict__ Bg,
                                           int K, int Ntot, int tid) {
#pragma unroll
    for (int q = 0; q < 4; q++)
        load_quarter(sbase, st, Ag, Bg, K, Ntot, tid, q);
}

// load one ks-step's fragments (warp tile 64x64); B via x4.trans
__device__ __forceinline__ void frag_load(uint32_t (&af)[4][4], uint32_t (&bf)[8][2],
                                          uint32_t sA, uint32_t sB, int ks,
                                          int wm, int wn,
                                          uint32_t a_lane_off, uint32_t b_lane_off) {
#pragma unroll
    for (int mt = 0; mt < 4; mt++) {
        ldsm_x4(af[mt], sA + (uint32_t)((wm * 64 + mt * 16) * A_ROW_B + ks * 32)
                        + a_lane_off);
    }
#pragma unroll
    for (int nt2 = 0; nt2 < 4; nt2++) {
        ldsm_x4_t(bf[2 * nt2][0], bf[2 * nt2][1],
                  bf[2 * nt2 + 1][0], bf[2 * nt2 + 1][1],
                  sB + (uint32_t)(ks * 16 * B_ROW_B + (wn * 64 + nt2 * 16) * 2)
                     + b_lane_off);
    }
}

// -------- GEMM: C[row,n] = sum_k A[row,k]*W[m,k,n] + bias[m,n] (fp16 in)
// HALF_OUT=1 -> fp16 output (GEMM1), else fp32 streaming stores (GEMM2).
// 128 threads = 4 warps (2m x 2n), warp tile 64x64, 2 CTAs/SM.
// Producer cp.async interleaved into the ks loop (quarter per ks step).
template <int HALF_OUT>
__launch_bounds__(NTHREADS, 2)
__global__ void gemm_f16(const __half* __restrict__ A,
                         const __half* __restrict__ W,
                         const float* __restrict__ bias,
                         float* __restrict__ Cf,
                         __half* __restrict__ Ch,
                         int K, int Ntot, int NT) {
    extern __shared__ __align__(16) char smc[];
    const uint32_t sbase = smem_u32(smc);

    const int tid  = threadIdx.x;
    const int lane = tid & 31;
    const int warp = tid >> 5;
    const int wm   = warp >> 1;      // 0..1
    const int wn   = warp & 1;       // 0..1
    const int g    = lane >> 2;      // 0..7
    const int r    = lane & 3;       // 0..3

    const int brow   = blockIdx.x * BM;   // row tile fastest
    const int bcol   = blockIdx.y * BN;
    const int member = brow >> 12;

    const __half* Ag0 = A + (size_t)brow * K;
    const __half* Bg0 = W + (size_t)member * K * Ntot + bcol;

    float acc[4][8][4];
#pragma unroll
    for (int i = 0; i < 4; i++)
#pragma unroll
        for (int j = 0; j < 8; j++)
#pragma unroll
            for (int c = 0; c < 4; c++) acc[i][j][c] = 0.f;

    const uint32_t a_lane_off =
        (uint32_t)((lane & 15) * A_ROW_B + (lane >> 4) * 16);
    const uint32_t b_lane_off =
        (uint32_t)((lane & 15) * B_ROW_B + (lane >> 4) * 16);

    // prologue: stage 0 = tile 0
    load_stage(sbase, 0, Ag0, Bg0, K, Ntot, tid);
    cp_commit();

    uint32_t af[2][4][4];
    uint32_t bf[2][8][2];

    for (int t = 0; t < NT; t++) {
        cp_wait0();          // tile t landed (only group pending)
        __syncthreads();     // visible to all; all done reading other buffer

        const uint32_t sA = sbase + (t & 1) * STAGE_B;
        const uint32_t sB = sA + A_ST_B;

        frag_load(af[0], bf[0], sA, sB, 0, wm, wn, a_lane_off, b_lane_off);

        const bool pf = (t + 1 < NT);
        const __half* AgN = Ag0 + (t + 1) * BK;
        const __half* BgN = Bg0 + (size_t)(t + 1) * BK * Ntot;
        const int nst = (t + 1) & 1;

        // ks loop: frag prefetch, MMA burst, then one producer quarter
#pragma unroll
        for (int ks = 0; ks < 4; ks++) {
            const int cur = ks & 1;
            if (ks < 3) {
                frag_load(af[cur ^ 1], bf[cur ^ 1], sA, sB, ks + 1,
                          wm, wn, a_lane_off, b_lane_off);
            }
#pragma unroll
            for (int mt = 0; mt < 4; mt++)
#pragma unroll
                for (int nt = 0; nt < 8; nt++)
                    mma_f16(acc[mt][nt], af[cur][mt], bf[cur][nt]);
            if (pf) {
                load_quarter(sbase, nst, AgN, BgN, K, Ntot, tid, ks);
            }
        }
        cp_commit();
    }

    // epilogue: bias + store
    const float* bm = bias + (size_t)member * Ntot + bcol;
#pragma unroll
    for (int mt = 0; mt < 4; mt++) {
        const int row0 = brow + wm * 64 + mt * 16 + g;
#pragma unroll
        for (int nt = 0; nt < 8; nt++) {
            const int col0 = bcol + wn * 64 + nt * 8 + r * 2;
            const float bx0 = __ldg(bm + (col0 - bcol));
            const float bx1 = __ldg(bm + (col0 - bcol) + 1);
            if (HALF_OUT) {
                __half2 v0 = __floats2half2_rn(acc[mt][nt][0] + bx0,
                                               acc[mt][nt][1] + bx1);
                __half2 v1 = __floats2half2_rn(acc[mt][nt][2] + bx0,
                                               acc[mt][nt][3] + bx1);
                *(__half2*)(Ch + (size_t)row0 * Ntot + col0) = v0;
                *(__half2*)(Ch + (size_t)(row0 + 8) * Ntot + col0) = v1;
            } else {
                float2 v0, v1;
                v0.x = acc[mt][nt][0] + bx0;
                v0.y = acc[mt][nt][1] + bx1;
                v1.x = acc[mt][nt][2] + bx0;
                v1.y = acc[mt][nt][3] + bx1;
                stcs_f2(Cf + (size_t)row0 * Ntot + col0, v0);
                stcs_f2(Cf + (size_t)(row0 + 8) * Ntot + col0, v1);
            }
        }
    }
}

// ---------------- pre-pass: all three fp32 -> fp16 conversions, one launch ----
#define XN8  (ROWS * E_DIM / 8)
#define W1N8 (MEMB * E_DIM * H_DIM / 8)
#define W2N8 (MEMB * H_DIM * V_DIM / 8)

__global__ void convert_all(const float* __restrict__ x,
                            const float* __restrict__ W1,
                            const float* __restrict__ W2) {
    int i = blockIdx.x * blockDim.x + threadIdx.x;
    const float* src;
    __half* dst;
    if (i < XN8) {
        src = x; dst = g_xh;
    } else if (i < XN8 + W1N8) {
        i -= XN8; src = W1; dst = g_w1h;
    } else {
        i -= XN8 + W1N8;
        if (i >= W2N8) return;
        src = W2; dst = g_w2h;
    }
    float4 a = ((const float4*)src)[2 * i];
    float4 b = ((const float4*)src)[2 * i + 1];
    __half2 h[4];
    h[0] = __floats2half2_rn(a.x, a.y);
    h[1] = __floats2half2_rn(a.z, a.w);
    h[2] = __floats2half2_rn(b.x, b.y);
    h[3] = __floats2half2_rn(b.z, b.w);
    ((uint4*)dst)[i] = *(uint4*)h;
}

// ------------- fused LayerNorm + SiLU; fp16 in (g_h16), fp16 out (g_hh) -----
// 128 threads/row, 8 halfs/thread; stats in fp32. (Round-12 proven version.)
__launch_bounds__(128)
__global__ void ln_silu_kernel(const float* __restrict__ ln_w,
                               const float* __restrict__ ln_b) {
    const int row = blockIdx.x;
    const int m   = row >> 12;
    const __half* hp = g_h16 + (size_t)row * H_DIM;
    __half* op = g_hh + (size_t)row * H_DIM;
    const int t = threadIdx.x;

    uint4 raw = *(const uint4*)(hp + t * 8);
    __half2 hv[4];
    *(uint4*)hv = raw;
    float xv[8];
#pragma unroll
    for (int i = 0; i < 4; i++) {
        float2 f = __half22float2(hv[i]);
        xv[2 * i] = f.x; xv[2 * i + 1] = f.y;
    }

    float s = 0.f, q = 0.f;
#pragma unroll
    for (int i = 0; i < 8; i++) { s += xv[i]; q += xv[i] * xv[i]; }
#pragma unroll
    for (int o = 16; o; o >>= 1) {
        s += __shfl_xor_sync(0xffffffffu, s, o);
        q += __shfl_xor_sync(0xffffffffu, q, o);
    }
    __shared__ float rs[4], rq[4];
    if ((t & 31) == 0) { rs[t >> 5] = s; rq[t >> 5] = q; }
    __syncthreads();
    s = rs[0] + rs[1] + rs[2] + rs[3];
    q = rq[0] + rq[1] + rq[2] + rq[3];

    const float mu  = s * (1.0f / H_DIM);
    const float var = q * (1.0f / H_DIM) - mu * mu;
    const float inv = rsqrtf(var + 1e-5f);

    const float4 w0 = *(const float4*)(ln_w + (size_t)m * H_DIM + t * 8);
    const float4 w1 = *(const float4*)(ln_w + (size_t)m * H_DIM + t * 8 + 4);
    const float4 b0 = *(const float4*)(ln_b + (size_t)m * H_DIM + t * 8);
    const float4 b1 = *(const float4*)(ln_b + (size_t)m * H_DIM + t * 8 + 4);
    const float wv[8] = {w0.x, w0.y, w0.z, w0.w, w1.x, w1.y, w1.z, w1.w};
    const float bv[8] = {b0.x, b0.y, b0.z, b0.w, b1.x, b1.y, b1.z, b1.w};

    float y[8];
#pragma unroll
    for (int i = 0; i < 8; i++) {
        float v = (xv[i] - mu) * inv * wv[i] + bv[i];
        y[i] = v / (1.f + __expf(-v));
    }
    __half2 o2[4];
#pragma unroll
    for (int i = 0; i < 4; i++) o2[i] = __floats2half2_rn(y[2 * i], y[2 * i + 1]);
    *(uint4*)(op + t * 8) = *(uint4*)o2;
}

// ---------------- launch ----------------
extern "C" void kernel_launch(void* const* d_in, const int* in_sizes, int n_in,
                              void* d_out, int out_size) {
    const float* x  = (const float*)d_in[0];
    const float* W1 = (const float*)d_in[1];
    const float* b1 = (const float*)d_in[2];
    const float* lw = (const float*)d_in[3];
    const float* lb = (const float*)d_in[4];
    const float* W2 = (const float*)d_in[5];
    const float* b2 = (const float*)d_in[6];
    float* out = (float*)d_out;

    __half *xh, *w1h, *w2h, *hh, *h16;
    cudaGetSymbolAddress((void**)&xh,  g_xh);
    cudaGetSymbolAddress((void**)&w1h, g_w1h);
    cudaGetSymbolAddress((void**)&w2h, g_w2h);
    cudaGetSymbolAddress((void**)&h16, g_h16);
    cudaGetSymbolAddress((void**)&hh,  g_hh);

    cudaFuncSetAttribute(gemm_f16<1>, cudaFuncAttributeMaxDynamicSharedMemorySize,
                         SMEM_TOTAL);
    cudaFuncSetAttribute(gemm_f16<0>, cudaFuncAttributeMaxDynamicSharedMemorySize,
                         SMEM_TOTAL);

    // pre-pass: fp32 -> fp16 (x, W1, W2 in one launch)
    const int total8 = XN8 + W1N8 + W2N8;
    convert_all<<<(total8 + 511) / 512, 512>>>(x, W1, W2);

    // GEMM1: [32768,512] x [8: 512->1024] -> h16 (+b1), fp16 out
    gemm_f16<1><<<dim3(ROWS / BM, H_DIM / BN), NTHREADS, SMEM_TOTAL>>>(
        xh, w1h, b1, nullptr, h16, E_DIM, H_DIM, E_DIM / BK);
    // LayerNorm + SiLU, fp16 -> fp16
    ln_silu_kernel<<<ROWS, 128>>>(lw, lb);
    // GEMM2: [32768,1024] x [8: 1024->4096] -> out (+b2), fp32 streaming out
    gemm_f16<0><<<dim3(ROWS / BM, V_DIM / BN), NTHREADS, SMEM_TOTAL>>>(
        hh, w2h, b2, out, nullptr, H_DIM, V_DIM, H_DIM / BK);
}

// round 16
// speedup vs baseline: 1.2293x; 1.0115x over previous
#include <cuda_runtime.h>
#include <cuda_fp16.h>
#include <cstdint>
#include <cstddef>

#define MEMB   8
#define BATCHI 4096
#define E_DIM  512
#define H_DIM  1024
#define V_DIM  4096
#define ROWS   (MEMB * BATCHI)   // 32768

// ---------------- scratch (device globals: allocation-free) ----------------
__device__ __half g_xh [(size_t)ROWS * E_DIM];          // fp16 x
__device__ __half g_w1h[(size_t)MEMB * E_DIM * H_DIM];  // fp16 W1
__device__ __half g_w2h[(size_t)MEMB * H_DIM * V_DIM];  // fp16 W2
__device__ __half g_h16[(size_t)ROWS * H_DIM];          // fp16 hidden (pre-LN)
__device__ __half g_hh [(size_t)ROWS * H_DIM];          // fp16 hidden (GEMM2 in)

// ---------------- helpers ----------------
__device__ __forceinline__ uint32_t smem_u32(const void* p) {
    uint32_t a;
    asm("{ .reg .u64 t; cvta.to.shared.u64 t, %1; cvt.u32.u64 %0, t; }"
        : "=r"(a) : "l"(p));
    return a;
}
__device__ __forceinline__ void cp16_cg(uint32_t s, const void* g) {   // L1-bypass
    asm volatile("cp.async.cg.shared.global [%0], [%1], 16;" :: "r"(s), "l"(g));
}
__device__ __forceinline__ void cp16_ca(uint32_t s, const void* g) {   // L1-alloc
    asm volatile("cp.async.ca.shared.global [%0], [%1], 16;" :: "r"(s), "l"(g));
}
__device__ __forceinline__ void cp_commit() {
    asm volatile("cp.async.commit_group;" ::: "memory");
}
__device__ __forceinline__ void cp_wait0() {
    asm volatile("cp.async.wait_group 0;" ::: "memory");
}
__device__ __forceinline__ void ldsm_x4(uint32_t (&r)[4], uint32_t addr) {
    asm volatile("ldmatrix.sync.aligned.m8n8.x4.shared.b16 {%0,%1,%2,%3}, [%4];"
                 : "=r"(r[0]), "=r"(r[1]), "=r"(r[2]), "=r"(r[3]) : "r"(addr));
}
// x4 transposed: two k-halves x two adjacent n-groups
__device__ __forceinline__ void ldsm_x4_t(uint32_t& r0, uint32_t& r1,
                                          uint32_t& r2, uint32_t& r3,
                                          uint32_t addr) {
    asm volatile("ldmatrix.sync.aligned.m8n8.x4.trans.shared.b16 {%0,%1,%2,%3}, [%4];"
                 : "=r"(r0), "=r"(r1), "=r"(r2), "=r"(r3) : "r"(addr));
}
__device__ __forceinline__ void mma_f16(float (&d)[4], const uint32_t (&a)[4],
                                        const uint32_t (&b)[2]) {
    asm volatile(
        "mma.sync.aligned.m16n8k16.row.col.f32.f16.f16.f32 "
        "{%0,%1,%2,%3}, {%4,%5,%6,%7}, {%8,%9}, {%0,%1,%2,%3};\n"
        : "+f"(d[0]), "+f"(d[1]), "+f"(d[2]), "+f"(d[3])
        : "r"(a[0]), "r"(a[1]), "r"(a[2]), "r"(a[3]), "r"(b[0]), "r"(b[1]));
}
__device__ __forceinline__ void stcs_f2(float* p, float2 v) {
    asm volatile("st.global.cs.v2.f32 [%0], {%1, %2};" :: "l"(p), "f"(v.x), "f"(v.y)
                 : "memory");
}

// ---------------- tiling (round-12 champion config) ----------------
#define BM   128
#define BN   128
#define BK   64            // fp16 k-depth per tile (4 ks steps of 16)
#define NTHREADS 128       // 4 warps (2m x 2n), warp tile 64x64
#define STAGES 2
#define A_ROW_B  144       // 64 halfs (128B) + 16B pad, conflict-free ldmatrix
#define B_ROW_B  272       // 128 halfs (256B) + 16B pad, conflict-free ldmatrix
#define A_ST_B   (BM * A_ROW_B)              // 18432
#define B_ST_B   (BK * B_ROW_B)              // 17408
#define STAGE_B  (A_ST_B + B_ST_B)           // 35840
#define SMEM_TOTAL (STAGES * STAGE_B)        // 71680 (x2 CTA = 143360)
#define A_CHUNKS (BM * BK * 2 / 16)          // 1024
#define B_CHUNKS (BK * BN * 2 / 16)          // 1024

#define XN8  (ROWS * E_DIM / 8)
#define W1N8 (MEMB * E_DIM * H_DIM / 8)
#define W2N8 (MEMB * H_DIM * V_DIM / 8)

#define G1_GEMM  ((ROWS / BM) * (H_DIM / BN))   // 2048 GEMM1 tiles
#define CONV_CTAS 512                           // W2-convert CTAs (1 per 4 gemm)
#define G1_TOTAL (G1_GEMM + CONV_CTAS)          // 2560, every 5th converts

// one stage of cp.async: 16 chunks/thread @ 128 threads.
// A via .cg (streaming); B via .ca (L1-cached, shared with co-resident CTA).
__device__ __forceinline__ void load_stage(uint32_t sbase, int st,
                                           const __half* __restrict__ Ag,
                                           const __half* __restrict__ Bg,
                                           int K, int Ntot, int tid) {
    const uint32_t sA = sbase + st * STAGE_B;
    const uint32_t sB = sA + A_ST_B;
#pragma unroll
    for (int j = 0; j < (A_CHUNKS + B_CHUNKS) / NTHREADS; j++) {
        const int c = tid + j * NTHREADS;
        if (c < A_CHUNKS) {
            const int row = c >> 3, q = c & 7;        // 8 chunks per A row
            cp16_cg(sA + (uint32_t)(row * A_ROW_B + q * 16),
                    Ag + (size_t)row * K + q * 8);
        } else {
            const int b = c - A_CHUNKS;
            const int k = b >> 4, q = b & 15;         // 16 chunks per B row
            cp16_ca(sB + (uint32_t)(k * B_ROW_B + q * 16),
                    Bg + (size_t)k * Ntot + q * 8);
        }
    }
}

// load one ks-step's fragments (warp tile 64x64); B via x4.trans
__device__ __forceinline__ void frag_load(uint32_t (&af)[4][4], uint32_t (&bf)[8][2],
                                          uint32_t sA, uint32_t sB, int ks,
                                          int wm, int wn,
                                          uint32_t a_lane_off, uint32_t b_lane_off) {
#pragma unroll
    for (int mt = 0; mt < 4; mt++) {
        ldsm_x4(af[mt], sA + (uint32_t)((wm * 64 + mt * 16) * A_ROW_B + ks * 32)
                        + a_lane_off);
    }
#pragma unroll
    for (int nt2 = 0; nt2 < 4; nt2++) {
        ldsm_x4_t(bf[2 * nt2][0], bf[2 * nt2][1],
                  bf[2 * nt2 + 1][0], bf[2 * nt2 + 1][1],
                  sB + (uint32_t)(ks * 16 * B_ROW_B + (wn * 64 + nt2 * 16) * 2)
                     + b_lane_off);
    }
}

// fp32 -> fp16, 8 elems at index i (of n8 total)
__device__ __forceinline__ void conv8(const float* __restrict__ src,
                                      __half* __restrict__ dst, int i) {
    float4 a = ((const float4*)src)[2 * i];
    float4 b = ((const float4*)src)[2 * i + 1];
    __half2 h[4];
    h[0] = __floats2half2_rn(a.x, a.y);
    h[1] = __floats2half2_rn(a.z, a.w);
    h[2] = __floats2half2_rn(b.x, b.y);
    h[3] = __floats2half2_rn(b.z, b.w);
    ((uint4*)dst)[i] = *(uint4*)h;
}

// -------- GEMM: C[row,n] = sum_k A[row,k]*W[m,k,n] + bias[m,n] (fp16 in)
// HALF_OUT=1: fp16 output (GEMM1), 1D grid with every 5th CTA converting a
//             W2 slice fp32->fp16 (hides convert under GEMM1's idle DRAM).
// HALF_OUT=0: fp32 streaming stores (GEMM2), 2D grid (row tile fastest).
// 128 threads = 4 warps (2m x 2n), warp tile 64x64, 2 CTAs/SM.
template <int HALF_OUT>
__launch_bounds__(NTHREADS, 2)
__global__ void gemm_f16(const __half* __restrict__ A,
                         const __half* __restrict__ W,
                         const float* __restrict__ bias,
                         float* __restrict__ Cf,
                         __half* __restrict__ Ch,
                         const float* __restrict__ W2src,
                         __half* __restrict__ W2dst,
                         int K, int Ntot, int NT) {
    extern __shared__ __align__(16) char smc[];
    const uint32_t sbase = smem_u32(smc);

    const int tid  = threadIdx.x;

    int brow, bcol;
    if (HALF_OUT) {
        const int bid = blockIdx.x;
        if ((bid % 5) == 4) {
            // -------- W2 converter CTA --------
            const int cidx = bid / 5;
            for (int i = cidx * NTHREADS + tid; i < W2N8;
                 i += CONV_CTAS * NTHREADS)
                conv8(W2src, W2dst, i);
            return;
        }
        const int gemmIdx = bid - bid / 5;
        brow = (gemmIdx & (ROWS / BM - 1)) * BM;
        bcol = (gemmIdx / (ROWS / BM)) * BN;
    } else {
        brow = blockIdx.x * BM;
        bcol = blockIdx.y * BN;
    }

    const int lane = tid & 31;
    const int warp = tid >> 5;
    const int wm   = warp >> 1;      // 0..1
    const int wn   = warp & 1;       // 0..1
    const int g    = lane >> 2;      // 0..7
    const int r    = lane & 3;       // 0..3
    const int member = brow >> 12;

    const __half* Ag0 = A + (size_t)brow * K;
    const __half* Bg0 = W + (size_t)member * K * Ntot + bcol;

    float acc[4][8][4];
#pragma unroll
    for (int i = 0; i < 4; i++)
#pragma unroll
        for (int j = 0; j < 8; j++)
#pragma unroll
            for (int c = 0; c < 4; c++) acc[i][j][c] = 0.f;

    const uint32_t a_lane_off =
        (uint32_t)((lane & 15) * A_ROW_B + (lane >> 4) * 16);
    const uint32_t b_lane_off =
        (uint32_t)((lane & 15) * B_ROW_B + (lane >> 4) * 16);

    // prologue: stage 0 = tile 0
    load_stage(sbase, 0, Ag0, Bg0, K, Ntot, tid);
    cp_commit();

    uint32_t af[2][4][4];
    uint32_t bf[2][8][2];

    for (int t = 0; t < NT; t++) {
        cp_wait0();          // tile t landed (only group pending)
        __syncthreads();     // visible to all; all done reading other buffer

        const uint32_t sA = sbase + (t & 1) * STAGE_B;
        const uint32_t sB = sA + A_ST_B;

        // ks0 LDSM first: latency hides under cp.async issue below
        frag_load(af[0], bf[0], sA, sB, 0, wm, wn, a_lane_off, b_lane_off);

        if (t + 1 < NT) {
            load_stage(sbase, (t + 1) & 1, Ag0 + (t + 1) * BK,
                       Bg0 + (size_t)(t + 1) * BK * Ntot, K, Ntot, tid);
        }
        cp_commit();

        // software-pipelined ks loop: prefetch ks+1 frags before ks MMAs
#pragma unroll
        for (int ks = 0; ks < 4; ks++) {
            const int cur = ks & 1;
            if (ks < 3) {
                frag_load(af[cur ^ 1], bf[cur ^ 1], sA, sB, ks + 1,
                          wm, wn, a_lane_off, b_lane_off);
            }
#pragma unroll
            for (int mt = 0; mt < 4; mt++)
#pragma unroll
                for (int nt = 0; nt < 8; nt++)
                    mma_f16(acc[mt][nt], af[cur][mt], bf[cur][nt]);
        }
    }

    // epilogue: bias + store
    const float* bm = bias + (size_t)member * Ntot + bcol;
#pragma unroll
    for (int mt = 0; mt < 4; mt++) {
        const int row0 = brow + wm * 64 + mt * 16 + g;
#pragma unroll
        for (int nt = 0; nt < 8; nt++) {
            const int col0 = bcol + wn * 64 + nt * 8 + r * 2;
            const float bx0 = __ldg(bm + (col0 - bcol));
            const float bx1 = __ldg(bm + (col0 - bcol) + 1);
            if (HALF_OUT) {
                __half2 v0 = __floats2half2_rn(acc[mt][nt][0] + bx0,
                                               acc[mt][nt][1] + bx1);
                __half2 v1 = __floats2half2_rn(acc[mt][nt][2] + bx0,
                                               acc[mt][nt][3] + bx1);
                *(__half2*)(Ch + (size_t)row0 * Ntot + col0) = v0;
                *(__half2*)(Ch + (size_t)(row0 + 8) * Ntot + col0) = v1;
            } else {
                float2 v0, v1;
                v0.x = acc[mt][nt][0] + bx0;
                v0.y = acc[mt][nt][1] + bx1;
                v1.x = acc[mt][nt][2] + bx0;
                v1.y = acc[mt][nt][3] + bx1;
                stcs_f2(Cf + (size_t)row0 * Ntot + col0, v0);
                stcs_f2(Cf + (size_t)(row0 + 8) * Ntot + col0, v1);
            }
        }
    }
}

// ---------------- pre-pass: x + W1 fp32 -> fp16 (one launch) ----------------
__global__ void convert_xw1(const float* __restrict__ x,
                            const float* __restrict__ W1) {
    int i = blockIdx.x * blockDim.x + threadIdx.x;
    if (i < XN8) {
        conv8(x, g_xh, i);
    } else {
        i -= XN8;
        if (i >= W1N8) return;
        conv8(W1, g_w1h, i);
    }
}

// ------------- fused LayerNorm + SiLU; fp16 in (g_h16), fp16 out (g_hh) -----
// 128 threads/row, 8 halfs/thread; stats in fp32. (Round-12 proven version.)
__launch_bounds__(128)
__global__ void ln_silu_kernel(const float* __restrict__ ln_w,
                               const float* __restrict__ ln_b) {
    const int row = blockIdx.x;
    const int m   = row >> 12;
    const __half* hp = g_h16 + (size_t)row * H_DIM;
    __half* op = g_hh + (size_t)row * H_DIM;
    const int t = threadIdx.x;

    uint4 raw = *(const uint4*)(hp + t * 8);
    __half2 hv[4];
    *(uint4*)hv = raw;
    float xv[8];
#pragma unroll
    for (int i = 0; i < 4; i++) {
        float2 f = __half22float2(hv[i]);
        xv[2 * i] = f.x; xv[2 * i + 1] = f.y;
    }

    float s = 0.f, q = 0.f;
#pragma unroll
    for (int i = 0; i < 8; i++) { s += xv[i]; q += xv[i] * xv[i]; }
#pragma unroll
    for (int o = 16; o; o >>= 1) {
        s += __shfl_xor_sync(0xffffffffu, s, o);
        q += __shfl_xor_sync(0xffffffffu, q, o);
    }
    __shared__ float rs[4], rq[4];
    if ((t & 31) == 0) { rs[t >> 5] = s; rq[t >> 5] = q; }
    __syncthreads();
    s = rs[0] + rs[1] + rs[2] + rs[3];
    q = rq[0] + rq[1] + rq[2] + rq[3];

    const float mu  = s * (1.0f / H_DIM);
    const float var = q * (1.0f / H_DIM) - mu * mu;
    const float inv = rsqrtf(var + 1e-5f);

    const float4 w0 = *(const float4*)(ln_w + (size_t)m * H_DIM + t * 8);
    const float4 w1 = *(const float4*)(ln_w + (size_t)m * H_DIM + t * 8 + 4);
    const float4 b0 = *(const float4*)(ln_b + (size_t)m * H_DIM + t * 8);
    const float4 b1 = *(const float4*)(ln_b + (size_t)m * H_DIM + t * 8 + 4);
    const float wv[8] = {w0.x, w0.y, w0.z, w0.w, w1.x, w1.y, w1.z, w1.w};
    const float bv[8] = {b0.x, b0.y, b0.z, b0.w, b1.x, b1.y, b1.z, b1.w};

    float y[8];
#pragma unroll
    for (int i = 0; i < 8; i++) {
        float v = (xv[i] - mu) * inv * wv[i] + bv[i];
        y[i] = v / (1.f + __expf(-v));
    }
    __half2 o2[4];
#pragma unroll
    for (int i = 0; i < 4; i++) o2[i] = __floats2half2_rn(y[2 * i], y[2 * i + 1]);
    *(uint4*)(op + t * 8) = *(uint4*)o2;
}

// ---------------- launch ----------------
extern "C" void kernel_launch(void* const* d_in, const int* in_sizes, int n_in,
                              void* d_out, int out_size) {
    const float* x  = (const float*)d_in[0];
    const float* W1 = (const float*)d_in[1];
    const float* b1 = (const float*)d_in[2];
    const float* lw = (const float*)d_in[3];
    const float* lb = (const float*)d_in[4];
    const float* W2 = (const float*)d_in[5];
    const float* b2 = (const float*)d_in[6];
    float* out = (float*)d_out;

    __half *xh, *w1h, *w2h, *hh, *h16;
    cudaGetSymbolAddress((void**)&xh,  g_xh);
    cudaGetSymbolAddress((void**)&w1h, g_w1h);
    cudaGetSymbolAddress((void**)&w2h, g_w2h);
    cudaGetSymbolAddress((void**)&h16, g_h16);
    cudaGetSymbolAddress((void**)&hh,  g_hh);

    cudaFuncSetAttribute(gemm_f16<1>, cudaFuncAttributeMaxDynamicSharedMemorySize,
                         SMEM_TOTAL);
    cudaFuncSetAttribute(gemm_f16<0>, cudaFuncAttributeMaxDynamicSharedMemorySize,
                         SMEM_TOTAL);

    // pre-pass: x + W1 only (W2 converts inside GEMM1's grid)
    convert_xw1<<<(XN8 + W1N8 + 511) / 512, 512>>>(x, W1);

    // GEMM1 (+ interleaved W2 convert CTAs): -> h16 (+b1), fp16 out
    gemm_f16<1><<<G1_TOTAL, NTHREADS, SMEM_TOTAL>>>(
        xh, w1h, b1, nullptr, h16, W2, w2h, E_DIM, H_DIM, E_DIM / BK);
    // LayerNorm + SiLU, fp16 -> fp16
    ln_silu_kernel<<<ROWS, 128>>>(lw, lb);
    // GEMM2: [32768,1024] x [8: 1024->4096] -> out (+b2), fp32 streaming out
    gemm_f16<0><<<dim3(ROWS / BM, V_DIM / BN), NTHREADS, SMEM_TOTAL>>>(
        hh, w2h, b2, out, nullptr, nullptr, nullptr, H_DIM, V_DIM, H_DIM / BK);
}